// round 1
// baseline (speedup 1.0000x reference)
#include <cuda_runtime.h>
#include <math.h>

// Problem constants
#define BB  2
#define SS  2048
#define DDIM 1024
#define HH  16
#define HDD 64
#define MM  (BB*SS)   // 4096

// Scratch: projected Q/K/V in [B,H,S,HD] layout, one per z in {q,k,v}
__device__ float g_qkv[3][(size_t)BB * HH * SS * HDD];

// ---------------------------------------------------------------------------
// Kernel 1: QKV projection GEMM.  Y = X @ W + b, reshaped to [B,H,S,HD].
// Tile: 64x64, BK=16, 256 threads, 4x4 per thread.
// grid = (N/64=16, M/64=64, 3)
// ---------------------------------------------------------------------------
__global__ __launch_bounds__(256) void qkv_proj_kernel(
    const float* __restrict__ q, const float* __restrict__ k, const float* __restrict__ v,
    const float* __restrict__ Wq, const float* __restrict__ bq,
    const float* __restrict__ Wk, const float* __restrict__ bk,
    const float* __restrict__ Wv, const float* __restrict__ bv)
{
    const int z = blockIdx.z;
    const float* X    = (z == 0) ? q  : (z == 1) ? k  : v;
    const float* W    = (z == 0) ? Wq : (z == 1) ? Wk : Wv;
    const float* bias = (z == 0) ? bq : (z == 1) ? bk : bv;
    float* out = g_qkv[z];

    __shared__ float Xs[16][65];   // k-major: Xs[kk][row]
    __shared__ float Ws[16][65];   // k-major: Ws[kk][col]

    const int tid = threadIdx.x;
    const int tx = tid % 16;
    const int ty = tid / 16;
    const int m0 = blockIdx.y * 64;
    const int n0 = blockIdx.x * 64;

    float acc[4][4] = {};

    // load index helpers
    const int lrow = tid / 4;          // 0..63  X-tile row
    const int lseg = tid % 4;          // 0..3   (4 floats each)
    const int wk   = tid / 16;         // 0..15  W-tile k row
    const int wn   = (tid % 16) * 4;   // 0..60

    for (int k0 = 0; k0 < DDIM; k0 += 16) {
        // X tile [64 rows x 16 k] -> Xs[k][row]  (transpose on store)
        float4 xv = *reinterpret_cast<const float4*>(
            &X[(size_t)(m0 + lrow) * DDIM + k0 + lseg * 4]);
        Xs[lseg * 4 + 0][lrow] = xv.x;
        Xs[lseg * 4 + 1][lrow] = xv.y;
        Xs[lseg * 4 + 2][lrow] = xv.z;
        Xs[lseg * 4 + 3][lrow] = xv.w;
        // W tile [16 k x 64 n] -> Ws[k][n]
        float4 wv = *reinterpret_cast<const float4*>(
            &W[(size_t)(k0 + wk) * DDIM + n0 + wn]);
        Ws[wk][wn + 0] = wv.x;
        Ws[wk][wn + 1] = wv.y;
        Ws[wk][wn + 2] = wv.z;
        Ws[wk][wn + 3] = wv.w;
        __syncthreads();

        #pragma unroll
        for (int kk = 0; kk < 16; kk++) {
            float a[4], b[4];
            #pragma unroll
            for (int i = 0; i < 4; i++) a[i] = Xs[kk][ty * 4 + i];
            #pragma unroll
            for (int j = 0; j < 4; j++) b[j] = Ws[kk][tx * 4 + j];
            #pragma unroll
            for (int i = 0; i < 4; i++)
                #pragma unroll
                for (int j = 0; j < 4; j++)
                    acc[i][j] += a[i] * b[j];
        }
        __syncthreads();
    }

    // epilogue: add bias, scatter into [B,H,S,HD]
    // n0 is 64-aligned and HD=64, so this tile maps to exactly one head.
    const int h = n0 / HDD;
    #pragma unroll
    for (int i = 0; i < 4; i++) {
        const int m  = m0 + ty * 4 + i;
        const int b_ = m / SS;
        const int s  = m % SS;
        float* orow = &out[(((size_t)b_ * HH + h) * SS + s) * HDD];
        #pragma unroll
        for (int j = 0; j < 4; j++) {
            const int n = tx * 4 + j;
            orow[n] = acc[i][j] + bias[n0 + n];
        }
    }
}

// ---------------------------------------------------------------------------
// Kernel 2: flash-attention style, fp32.
// One CTA = 64-query tile of one (b,h).  grid = (S/64=32, B*H=32), 256 threads.
// smem: Qs(64x65) | Ks(64x65, aliased by P after scores) | Vs(64x65)
// ---------------------------------------------------------------------------
#define PS 65  // row pitch in floats (padding kills smem bank conflicts)

__global__ __launch_bounds__(256) void attn_kernel(float* __restrict__ out)
{
    extern __shared__ float sm[];
    float* Qs = sm;                // 64 * PS
    float* Ks = sm + 64 * PS;      // K tile; reused as P tile after scores
    float* Vs = sm + 2 * 64 * PS;

    const int tid = threadIdx.x;
    const int tx  = tid % 16;
    const int ty  = tid / 16;
    const int q0  = blockIdx.x * 64;
    const int bh  = blockIdx.y;

    const float* Qg = &g_qkv[0][(size_t)bh * SS * HDD];
    const float* Kg = &g_qkv[1][(size_t)bh * SS * HDD];
    const float* Vg = &g_qkv[2][(size_t)bh * SS * HDD];

    // load Q tile (coalesced: 16 lanes cover one 256B row)
    {
        const int r  = tid / 16;        // 0..15
        const int c4 = (tid % 16) * 4;  // 0..60
        #pragma unroll
        for (int p = 0; p < 4; p++) {
            const int row = r + p * 16;
            float4 val = *reinterpret_cast<const float4*>(
                &Qg[(size_t)(q0 + row) * HDD + c4]);
            float* dst = &Qs[row * PS + c4];
            dst[0] = val.x; dst[1] = val.y; dst[2] = val.z; dst[3] = val.w;
        }
    }

    float m_i[4], l_i[4];
    float o[4][4] = {};
    #pragma unroll
    for (int i = 0; i < 4; i++) { m_i[i] = -INFINITY; l_i[i] = 0.0f; }

    const float scale = 0.125f;   // 1/sqrt(64)

    for (int kt = 0; kt < SS; kt += 64) {
        __syncthreads();  // prev iter's P/V reads done; also orders Q load on iter 0

        // load K and V tiles
        {
            const int r  = tid / 16;
            const int c4 = (tid % 16) * 4;
            #pragma unroll
            for (int p = 0; p < 4; p++) {
                const int row = r + p * 16;
                float4 kv = *reinterpret_cast<const float4*>(
                    &Kg[(size_t)(kt + row) * HDD + c4]);
                float* dk = &Ks[row * PS + c4];
                dk[0] = kv.x; dk[1] = kv.y; dk[2] = kv.z; dk[3] = kv.w;
                float4 vv = *reinterpret_cast<const float4*>(
                    &Vg[(size_t)(kt + row) * HDD + c4]);
                float* dv = &Vs[row * PS + c4];
                dv[0] = vv.x; dv[1] = vv.y; dv[2] = vv.z; dv[3] = vv.w;
            }
        }
        __syncthreads();

        // scores s = (Q @ K^T) * scale   (4x4 per thread)
        float s[4][4] = {};
        #pragma unroll 8
        for (int kk = 0; kk < HDD; kk++) {
            float a[4], b[4];
            #pragma unroll
            for (int i = 0; i < 4; i++) a[i] = Qs[(ty * 4 + i) * PS + kk];
            #pragma unroll
            for (int j = 0; j < 4; j++) b[j] = Ks[(tx * 4 + j) * PS + kk];
            #pragma unroll
            for (int i = 0; i < 4; i++)
                #pragma unroll
                for (int j = 0; j < 4; j++)
                    s[i][j] += a[i] * b[j];
        }

        // online softmax (row groups = 16 lanes sharing ty; xor-shuffles stay in group)
        #pragma unroll
        for (int i = 0; i < 4; i++) {
            float mx = -INFINITY;
            #pragma unroll
            for (int j = 0; j < 4; j++) {
                s[i][j] *= scale;
                mx = fmaxf(mx, s[i][j]);
            }
            #pragma unroll
            for (int d = 1; d < 16; d <<= 1)
                mx = fmaxf(mx, __shfl_xor_sync(0xffffffffu, mx, d));

            const float m_new = fmaxf(m_i[i], mx);
            const float alpha = __expf(m_i[i] - m_new);
            float rs = 0.0f;
            #pragma unroll
            for (int j = 0; j < 4; j++) {
                const float p = __expf(s[i][j] - m_new);
                s[i][j] = p;
                rs += p;
            }
            #pragma unroll
            for (int d = 1; d < 16; d <<= 1)
                rs += __shfl_xor_sync(0xffffffffu, rs, d);

            l_i[i] = l_i[i] * alpha + rs;
            m_i[i] = m_new;
            #pragma unroll
            for (int j = 0; j < 4; j++) o[i][j] *= alpha;
        }

        __syncthreads();  // all threads done reading Ks before overwriting with P
        #pragma unroll
        for (int i = 0; i < 4; i++)
            #pragma unroll
            for (int j = 0; j < 4; j++)
                Ks[(ty * 4 + i) * PS + (tx * 4 + j)] = s[i][j];
        __syncthreads();

        // O += P @ V
        #pragma unroll 8
        for (int kk = 0; kk < 64; kk++) {
            float a[4], b[4];
            #pragma unroll
            for (int i = 0; i < 4; i++) a[i] = Ks[(ty * 4 + i) * PS + kk];
            #pragma unroll
            for (int j = 0; j < 4; j++) b[j] = Vs[kk * PS + tx * 4 + j];
            #pragma unroll
            for (int i = 0; i < 4; i++)
                #pragma unroll
                for (int j = 0; j < 4; j++)
                    o[i][j] += a[i] * b[j];
        }
    }

    // epilogue: normalize and write merged-head output [B,S,D]
    const int b_ = bh / HH;
    const int h  = bh % HH;
    #pragma unroll
    for (int i = 0; i < 4; i++) {
        const int srow = q0 + ty * 4 + i;
        const float inv = 1.0f / l_i[i];
        float4 val;
        val.x = o[i][0] * inv;
        val.y = o[i][1] * inv;
        val.z = o[i][2] * inv;
        val.w = o[i][3] * inv;
        *reinterpret_cast<float4*>(
            &out[((size_t)b_ * SS + srow) * DDIM + h * HDD + tx * 4]) = val;
    }
}

// ---------------------------------------------------------------------------
// Launch
// ---------------------------------------------------------------------------
extern "C" void kernel_launch(void* const* d_in, const int* in_sizes, int n_in,
                              void* d_out, int out_size)
{
    (void)in_sizes; (void)n_in; (void)out_size;
    const float* q  = (const float*)d_in[0];
    const float* k  = (const float*)d_in[1];
    const float* v  = (const float*)d_in[2];
    const float* Wq = (const float*)d_in[3];
    const float* bq = (const float*)d_in[4];
    const float* Wk = (const float*)d_in[5];
    const float* bk = (const float*)d_in[6];
    const float* Wv = (const float*)d_in[7];
    const float* bv = (const float*)d_in[8];
    float* out = (float*)d_out;

    // QKV projections
    dim3 ggrid(DDIM / 64, MM / 64, 3);
    qkv_proj_kernel<<<ggrid, 256>>>(q, k, v, Wq, bq, Wk, bk, Wv, bv);

    // Attention
    const size_t smem = (size_t)3 * 64 * PS * sizeof(float);  // 49,920 B
    cudaFuncSetAttribute(attn_kernel,
                         cudaFuncAttributeMaxDynamicSharedMemorySize, (int)smem);
    attn_kernel<<<dim3(SS / 64, BB * HH), 256, smem>>>(out);
}

// round 4
// speedup vs baseline: 3.8325x; 3.8325x over previous
#include <cuda_runtime.h>
#include <math.h>
#include <stdint.h>

// Problem constants
#define BB   2
#define SS   2048
#define DDIM 1024
#define HH   16
#define HDD  64
#define MM   (BB*SS)   // 4096

// Scratch: Q,K in [b][h][s][hd]; V pre-transposed to [b][h][hd][s]
__device__ float g_qkv[3][(size_t)BB * HH * SS * HDD];

// ---------------------------------------------------------------------------
// helpers
// ---------------------------------------------------------------------------
__device__ __forceinline__ float to_tf32(float x) {
    uint32_t u;
    asm("cvt.rna.tf32.f32 %0, %1;" : "=r"(u) : "f"(x));
    return __uint_as_float(u);
}

__device__ __forceinline__ void mma_tf32(float c[4],
                                         uint32_t a0, uint32_t a1, uint32_t a2, uint32_t a3,
                                         uint32_t b0, uint32_t b1) {
    asm volatile(
        "mma.sync.aligned.m16n8k8.row.col.f32.tf32.tf32.f32 "
        "{%0,%1,%2,%3}, {%4,%5,%6,%7}, {%8,%9}, {%0,%1,%2,%3};"
        : "+f"(c[0]), "+f"(c[1]), "+f"(c[2]), "+f"(c[3])
        : "r"(a0), "r"(a1), "r"(a2), "r"(a3), "r"(b0), "r"(b1));
}

__device__ __forceinline__ uint32_t ldsf(const float* p) {
    return __float_as_uint(*p);
}

// ---------------------------------------------------------------------------
// Kernel 1: QKV projection, tf32 tensor cores.
// CTA tile 128(M) x 128(N), BK=32, 256 threads = 8 warps (4 M x 2 N),
// warp tile 32x64 (2 m16-tiles x 8 n8-tiles).
// z==2 (V) is written transposed: [b][h][hd][s].
// ---------------------------------------------------------------------------
#define XP 36    // Xs pitch (== 4 mod 32 -> conflict-free A-frag loads)
#define WP 136   // Ws pitch (== 8 mod 32 -> conflict-free B-frag loads; >=128 cols)

__global__ __launch_bounds__(256) void qkv_proj_kernel(
    const float* __restrict__ q, const float* __restrict__ k, const float* __restrict__ v,
    const float* __restrict__ Wq, const float* __restrict__ bq,
    const float* __restrict__ Wk, const float* __restrict__ bk,
    const float* __restrict__ Wv, const float* __restrict__ bv)
{
    const int z = blockIdx.z;
    const float* X    = (z == 0) ? q  : (z == 1) ? k  : v;
    const float* W    = (z == 0) ? Wq : (z == 1) ? Wk : Wv;
    const float* bias = (z == 0) ? bq : (z == 1) ? bk : bv;
    float* out = g_qkv[z];

    __shared__ float Xs[128][XP];
    __shared__ float Ws[32][WP];

    const int tid  = threadIdx.x;
    const int wid  = tid >> 5;
    const int lane = tid & 31;
    const int g    = lane >> 2;   // 0..7
    const int t    = lane & 3;    // 0..3
    const int wm   = wid & 3;     // warp M index 0..3
    const int wn   = wid >> 2;    // warp N index 0..1

    const int m0 = blockIdx.y * 128;
    const int n0 = blockIdx.x * 128;

    float acc[2][8][4];
    #pragma unroll
    for (int mi = 0; mi < 2; mi++)
        #pragma unroll
        for (int nt = 0; nt < 8; nt++)
            #pragma unroll
            for (int i = 0; i < 4; i++) acc[mi][nt][i] = 0.0f;

    // load mappings
    const int xm  = tid >> 3;          // 0..31 (X row, +j*32)
    const int xk4 = (tid & 7) * 4;     // 0..28
    const int wk  = tid >> 5;          // 0..7 (W k row, +j*8)
    const int wn4 = (tid & 31) * 4;    // 0..124

    for (int k0 = 0; k0 < DDIM; k0 += 32) {
        __syncthreads();
        // X tile 128x32 -> Xs[m][k]
        #pragma unroll
        for (int j = 0; j < 4; j++) {
            const int m = xm + j * 32;
            float4 xv = *reinterpret_cast<const float4*>(
                &X[(size_t)(m0 + m) * DDIM + k0 + xk4]);
            float4 o4;
            o4.x = to_tf32(xv.x); o4.y = to_tf32(xv.y);
            o4.z = to_tf32(xv.z); o4.w = to_tf32(xv.w);
            *reinterpret_cast<float4*>(&Xs[m][xk4]) = o4;
        }
        // W tile 32x128 -> Ws[k][n]
        #pragma unroll
        for (int j = 0; j < 4; j++) {
            const int kk = wk + j * 8;
            float4 wv = *reinterpret_cast<const float4*>(
                &W[(size_t)(k0 + kk) * DDIM + n0 + wn4]);
            float4 o4;
            o4.x = to_tf32(wv.x); o4.y = to_tf32(wv.y);
            o4.z = to_tf32(wv.z); o4.w = to_tf32(wv.w);
            *reinterpret_cast<float4*>(&Ws[kk][wn4]) = o4;
        }
        __syncthreads();

        #pragma unroll
        for (int ks = 0; ks < 4; ks++) {
            const int kk = ks * 8;
            uint32_t a[2][4];
            #pragma unroll
            for (int mi = 0; mi < 2; mi++) {
                const int rb = wm * 32 + mi * 16;
                a[mi][0] = ldsf(&Xs[rb + g    ][kk + t    ]);
                a[mi][1] = ldsf(&Xs[rb + 8 + g][kk + t    ]);
                a[mi][2] = ldsf(&Xs[rb + g    ][kk + t + 4]);
                a[mi][3] = ldsf(&Xs[rb + 8 + g][kk + t + 4]);
            }
            uint32_t b[8][2];
            #pragma unroll
            for (int nt = 0; nt < 8; nt++) {
                const int cb = wn * 64 + nt * 8 + g;
                b[nt][0] = ldsf(&Ws[kk + t    ][cb]);
                b[nt][1] = ldsf(&Ws[kk + t + 4][cb]);
            }
            #pragma unroll
            for (int mi = 0; mi < 2; mi++)
                #pragma unroll
                for (int nt = 0; nt < 8; nt++)
                    mma_tf32(acc[mi][nt], a[mi][0], a[mi][1], a[mi][2], a[mi][3],
                             b[nt][0], b[nt][1]);
        }
    }

    // epilogue
    #pragma unroll
    for (int mi = 0; mi < 2; mi++) {
        const int row0 = m0 + wm * 32 + mi * 16 + g;
        const int row1 = row0 + 8;
        #pragma unroll
        for (int nt = 0; nt < 8; nt++) {
            const int col = n0 + wn * 64 + nt * 8 + 2 * t;
            const float b0 = bias[col], b1 = bias[col + 1];
            const int h  = col >> 6;        // col/64
            const int hd = col & 63;
            const int b_0 = row0 >> 11, s0 = row0 & 2047;
            const int b_1 = row1 >> 11, s1 = row1 & 2047;
            if (z < 2) {
                // [b][h][s][hd]
                float2 v0 = make_float2(acc[mi][nt][0] + b0, acc[mi][nt][1] + b1);
                float2 v1 = make_float2(acc[mi][nt][2] + b0, acc[mi][nt][3] + b1);
                *reinterpret_cast<float2*>(
                    &out[(((size_t)b_0 * HH + h) * SS + s0) * HDD + hd]) = v0;
                *reinterpret_cast<float2*>(
                    &out[(((size_t)b_1 * HH + h) * SS + s1) * HDD + hd]) = v1;
            } else {
                // V transposed: [b][h][hd][s]
                const size_t base0 = ((size_t)b_0 * HH + h) * HDD;
                const size_t base1 = ((size_t)b_1 * HH + h) * HDD;
                out[(base0 + hd    ) * SS + s0] = acc[mi][nt][0] + b0;
                out[(base0 + hd + 1) * SS + s0] = acc[mi][nt][1] + b1;
                out[(base1 + hd    ) * SS + s1] = acc[mi][nt][2] + b0;
                out[(base1 + hd + 1) * SS + s1] = acc[mi][nt][3] + b1;
            }
        }
    }
}

// ---------------------------------------------------------------------------
// Kernel 2: flash attention, tf32 tensor cores.
// CTA = 128 queries of one (b,h); 4 warps, warp = 32 queries (2 m16 tiles).
// Key tiles of 64.  grid = (16, 32), 128 threads.
// smem (floats, pitch 68 == 4 mod 32):
//   Qs[128][68] | Ks[64][68] | Vts[64][68] | Ps[128][68]
// ---------------------------------------------------------------------------
#define AP 68
#define QS_OFF 0
#define KS_OFF (128 * AP)
#define VS_OFF (KS_OFF + 64 * AP)
#define PS_OFF (VS_OFF + 64 * AP)
#define ATTN_SMEM_FLOATS (PS_OFF + 128 * AP)

__global__ __launch_bounds__(128) void attn_kernel(float* __restrict__ out)
{
    extern __shared__ float sm[];
    float* Qs  = sm + QS_OFF;
    float* Ks  = sm + KS_OFF;
    float* Vts = sm + VS_OFF;
    float* Ps  = sm + PS_OFF;

    const int tid  = threadIdx.x;
    const int wid  = tid >> 5;
    const int lane = tid & 31;
    const int g    = lane >> 2;
    const int t    = lane & 3;
    const int q0   = blockIdx.x * 128;
    const int bh   = blockIdx.y;
    const int wq   = wid * 32;          // warp query base within CTA

    const float* Qg = g_qkv[0] + (size_t)bh * SS * HDD;   // [s][hd]
    const float* Kg = g_qkv[1] + (size_t)bh * SS * HDD;   // [s][hd]
    const float* Vg = g_qkv[2] + (size_t)bh * HDD * SS;   // [hd][s] (transposed)

    // load Q tile (scaled by 1/sqrt(hd), tf32-rounded)
    {
        const int hd4 = (tid & 15) * 4;
        const int rb  = tid >> 4;       // 0..7
        #pragma unroll
        for (int j = 0; j < 16; j++) {
            const int row = rb + j * 8;
            float4 v = *reinterpret_cast<const float4*>(
                &Qg[(size_t)(q0 + row) * HDD + hd4]);
            float4 o4;
            o4.x = to_tf32(v.x * 0.125f); o4.y = to_tf32(v.y * 0.125f);
            o4.z = to_tf32(v.z * 0.125f); o4.w = to_tf32(v.w * 0.125f);
            *reinterpret_cast<float4*>(&Qs[row * AP + hd4]) = o4;
        }
    }

    float o[2][8][4];
    float m_st[2][2], l_st[2][2];
    #pragma unroll
    for (int mi = 0; mi < 2; mi++) {
        m_st[mi][0] = -INFINITY; m_st[mi][1] = -INFINITY;
        l_st[mi][0] = 0.0f;      l_st[mi][1] = 0.0f;
        #pragma unroll
        for (int nt = 0; nt < 8; nt++)
            #pragma unroll
            for (int i = 0; i < 4; i++) o[mi][nt][i] = 0.0f;
    }

    for (int kt = 0; kt < SS; kt += 64) {
        __syncthreads();
        // K tile [key][hd], V tile [hd][key]
        {
            const int c4 = (tid & 15) * 4;
            const int rb = tid >> 4;
            #pragma unroll
            for (int j = 0; j < 8; j++) {
                const int r = rb + j * 8;   // 0..63
                float4 kv = *reinterpret_cast<const float4*>(
                    &Kg[(size_t)(kt + r) * HDD + c4]);
                float4 k4;
                k4.x = to_tf32(kv.x); k4.y = to_tf32(kv.y);
                k4.z = to_tf32(kv.z); k4.w = to_tf32(kv.w);
                *reinterpret_cast<float4*>(&Ks[r * AP + c4]) = k4;
                float4 vv = *reinterpret_cast<const float4*>(
                    &Vg[(size_t)r * SS + kt + c4]);
                float4 v4;
                v4.x = to_tf32(vv.x); v4.y = to_tf32(vv.y);
                v4.z = to_tf32(vv.z); v4.w = to_tf32(vv.w);
                *reinterpret_cast<float4*>(&Vts[r * AP + c4]) = v4;
            }
        }
        __syncthreads();

        // scores S = Qs @ Ks^T   (contraction over hd)
        float s[2][8][4];
        #pragma unroll
        for (int mi = 0; mi < 2; mi++)
            #pragma unroll
            for (int nt = 0; nt < 8; nt++)
                #pragma unroll
                for (int i = 0; i < 4; i++) s[mi][nt][i] = 0.0f;

        #pragma unroll
        for (int ks = 0; ks < 8; ks++) {
            const int kk = ks * 8;
            uint32_t a[2][4];
            #pragma unroll
            for (int mi = 0; mi < 2; mi++) {
                const int rb = wq + mi * 16;
                a[mi][0] = ldsf(&Qs[(rb + g    ) * AP + kk + t    ]);
                a[mi][1] = ldsf(&Qs[(rb + 8 + g) * AP + kk + t    ]);
                a[mi][2] = ldsf(&Qs[(rb + g    ) * AP + kk + t + 4]);
                a[mi][3] = ldsf(&Qs[(rb + 8 + g) * AP + kk + t + 4]);
            }
            uint32_t b[8][2];
            #pragma unroll
            for (int nt = 0; nt < 8; nt++) {
                b[nt][0] = ldsf(&Ks[(nt * 8 + g) * AP + kk + t    ]);
                b[nt][1] = ldsf(&Ks[(nt * 8 + g) * AP + kk + t + 4]);
            }
            #pragma unroll
            for (int mi = 0; mi < 2; mi++)
                #pragma unroll
                for (int nt = 0; nt < 8; nt++)
                    mma_tf32(s[mi][nt], a[mi][0], a[mi][1], a[mi][2], a[mi][3],
                             b[nt][0], b[nt][1]);
        }

        // online softmax (rows g / g+8 per m-tile; quad reductions)
        #pragma unroll
        for (int mi = 0; mi < 2; mi++) {
            float mx0 = -INFINITY, mx1 = -INFINITY;
            #pragma unroll
            for (int nt = 0; nt < 8; nt++) {
                mx0 = fmaxf(mx0, fmaxf(s[mi][nt][0], s[mi][nt][1]));
                mx1 = fmaxf(mx1, fmaxf(s[mi][nt][2], s[mi][nt][3]));
            }
            mx0 = fmaxf(mx0, __shfl_xor_sync(0xffffffffu, mx0, 1));
            mx0 = fmaxf(mx0, __shfl_xor_sync(0xffffffffu, mx0, 2));
            mx1 = fmaxf(mx1, __shfl_xor_sync(0xffffffffu, mx1, 1));
            mx1 = fmaxf(mx1, __shfl_xor_sync(0xffffffffu, mx1, 2));

            const float mn0 = fmaxf(m_st[mi][0], mx0);
            const float mn1 = fmaxf(m_st[mi][1], mx1);
            const float al0 = __expf(m_st[mi][0] - mn0);
            const float al1 = __expf(m_st[mi][1] - mn1);
            m_st[mi][0] = mn0; m_st[mi][1] = mn1;

            float sum0 = 0.0f, sum1 = 0.0f;
            #pragma unroll
            for (int nt = 0; nt < 8; nt++) {
                s[mi][nt][0] = __expf(s[mi][nt][0] - mn0);
                s[mi][nt][1] = __expf(s[mi][nt][1] - mn0);
                s[mi][nt][2] = __expf(s[mi][nt][2] - mn1);
                s[mi][nt][3] = __expf(s[mi][nt][3] - mn1);
                sum0 += s[mi][nt][0] + s[mi][nt][1];
                sum1 += s[mi][nt][2] + s[mi][nt][3];
            }
            sum0 += __shfl_xor_sync(0xffffffffu, sum0, 1);
            sum0 += __shfl_xor_sync(0xffffffffu, sum0, 2);
            sum1 += __shfl_xor_sync(0xffffffffu, sum1, 1);
            sum1 += __shfl_xor_sync(0xffffffffu, sum1, 2);

            l_st[mi][0] = l_st[mi][0] * al0 + sum0;
            l_st[mi][1] = l_st[mi][1] * al1 + sum1;

            #pragma unroll
            for (int nt = 0; nt < 8; nt++) {
                o[mi][nt][0] *= al0; o[mi][nt][1] *= al0;
                o[mi][nt][2] *= al1; o[mi][nt][3] *= al1;
            }
        }

        // store P (tf32) to per-warp region of Ps
        __syncwarp();
        #pragma unroll
        for (int mi = 0; mi < 2; mi++) {
            const int r0 = wq + mi * 16 + g;
            const int r1 = r0 + 8;
            #pragma unroll
            for (int nt = 0; nt < 8; nt++) {
                const int c = nt * 8 + 2 * t;
                float2 p0 = make_float2(to_tf32(s[mi][nt][0]), to_tf32(s[mi][nt][1]));
                float2 p1 = make_float2(to_tf32(s[mi][nt][2]), to_tf32(s[mi][nt][3]));
                *reinterpret_cast<float2*>(&Ps[r0 * AP + c]) = p0;
                *reinterpret_cast<float2*>(&Ps[r1 * AP + c]) = p1;
            }
        }
        __syncwarp();

        // O += P @ V   (contraction over key)
        #pragma unroll
        for (int ks = 0; ks < 8; ks++) {
            const int kk = ks * 8;
            uint32_t a[2][4];
            #pragma unroll
            for (int mi = 0; mi < 2; mi++) {
                const int rb = wq + mi * 16;
                a[mi][0] = ldsf(&Ps[(rb + g    ) * AP + kk + t    ]);
                a[mi][1] = ldsf(&Ps[(rb + 8 + g) * AP + kk + t    ]);
                a[mi][2] = ldsf(&Ps[(rb + g    ) * AP + kk + t + 4]);
                a[mi][3] = ldsf(&Ps[(rb + 8 + g) * AP + kk + t + 4]);
            }
            uint32_t b[8][2];
            #pragma unroll
            for (int nt = 0; nt < 8; nt++) {
                b[nt][0] = ldsf(&Vts[(nt * 8 + g) * AP + kk + t    ]);
                b[nt][1] = ldsf(&Vts[(nt * 8 + g) * AP + kk + t + 4]);
            }
            #pragma unroll
            for (int mi = 0; mi < 2; mi++)
                #pragma unroll
                for (int nt = 0; nt < 8; nt++)
                    mma_tf32(o[mi][nt], a[mi][0], a[mi][1], a[mi][2], a[mi][3],
                             b[nt][0], b[nt][1]);
        }
    }

    // epilogue: normalize, merge heads: out[b][s][h*64 + hd]
    const int b_ = bh >> 4;
    const int h  = bh & 15;
    #pragma unroll
    for (int mi = 0; mi < 2; mi++) {
        const float inv0 = 1.0f / l_st[mi][0];
        const float inv1 = 1.0f / l_st[mi][1];
        const int s0 = q0 + wq + mi * 16 + g;
        const int s1 = s0 + 8;
        #pragma unroll
        for (int nt = 0; nt < 8; nt++) {
            const int col = h * HDD + nt * 8 + 2 * t;
            float2 v0 = make_float2(o[mi][nt][0] * inv0, o[mi][nt][1] * inv0);
            float2 v1 = make_float2(o[mi][nt][2] * inv1, o[mi][nt][3] * inv1);
            *reinterpret_cast<float2*>(&out[((size_t)b_ * SS + s0) * DDIM + col]) = v0;
            *reinterpret_cast<float2*>(&out[((size_t)b_ * SS + s1) * DDIM + col]) = v1;
        }
    }
}

// ---------------------------------------------------------------------------
// Launch
// ---------------------------------------------------------------------------
extern "C" void kernel_launch(void* const* d_in, const int* in_sizes, int n_in,
                              void* d_out, int out_size)
{
    (void)in_sizes; (void)n_in; (void)out_size;
    const float* q  = (const float*)d_in[0];
    const float* k  = (const float*)d_in[1];
    const float* v  = (const float*)d_in[2];
    const float* Wq = (const float*)d_in[3];
    const float* bq = (const float*)d_in[4];
    const float* Wk = (const float*)d_in[5];
    const float* bk = (const float*)d_in[6];
    const float* Wv = (const float*)d_in[7];
    const float* bv = (const float*)d_in[8];
    float* out = (float*)d_out;

    dim3 ggrid(DDIM / 128, MM / 128, 3);   // (8, 32, 3)
    qkv_proj_kernel<<<ggrid, 256>>>(q, k, v, Wq, bq, Wk, bk, Wv, bv);

    const size_t smem = (size_t)ATTN_SMEM_FLOATS * sizeof(float);  // 104,448 B
    cudaFuncSetAttribute(attn_kernel,
                         cudaFuncAttributeMaxDynamicSharedMemorySize, (int)smem);
    attn_kernel<<<dim3(SS / 128, BB * HH), 128, smem>>>(out);
}